// round 12
// baseline (speedup 1.0000x reference)
#include <cuda_runtime.h>
#include <cuda_bf16.h>
#include <math.h>
#include <cstdint>

#define NN 50000
#define DH 128
#define EE 600000

// ---------------- scratch ------------------------------------------------------
__device__ float g_x[NN * DH];       // x1 (head out)
__device__ float g_h[NN * DH];       // h1
__device__ float g_z[NN];
__device__ float g_stats[2];
__device__ int   g_deg[NN];
__device__ int   g_rowstart[NN + 1];
__device__ int   g_cursor[NN];
__device__ int   g_adj[EE];
__device__ float g_WF[DH * DH];
__device__ float g_bf[DH];
__device__ float g_v2[DH];
__device__ float g_zb[1];
__device__ uint16_t g_Whi[6 * 16384];
__device__ uint16_t g_Wlo[6 * 16384];

// ---------------- helpers ------------------------------------------------------
__device__ __forceinline__ uint32_t smem_u32(const void* p) {
    uint32_t a;
    asm("{ .reg .u64 t; cvta.to.shared.u64 t, %1; cvt.u32.u64 %0, t; }" : "=r"(a) : "l"(p));
    return a;
}
__device__ __forceinline__ void ldsm_x4(uint32_t* r, uint32_t addr) {
    asm volatile("ldmatrix.sync.aligned.m8n8.x4.shared.b16 {%0,%1,%2,%3}, [%4];"
                 : "=r"(r[0]), "=r"(r[1]), "=r"(r[2]), "=r"(r[3]) : "r"(addr));
}
__device__ __forceinline__ void ldsm_x4_t(uint32_t* r, uint32_t addr) {
    asm volatile("ldmatrix.sync.aligned.m8n8.x4.trans.shared.b16 {%0,%1,%2,%3}, [%4];"
                 : "=r"(r[0]), "=r"(r[1]), "=r"(r[2]), "=r"(r[3]) : "r"(addr));
}
__device__ __forceinline__ void mma16816(float* d, const uint32_t* a, const uint32_t* b) {
    asm volatile(
        "mma.sync.aligned.m16n8k16.row.col.f32.bf16.bf16.f32 "
        "{%0,%1,%2,%3}, {%4,%5,%6,%7}, {%8,%9}, {%0,%1,%2,%3};"
        : "+f"(d[0]), "+f"(d[1]), "+f"(d[2]), "+f"(d[3])
        : "r"(a[0]), "r"(a[1]), "r"(a[2]), "r"(a[3]), "r"(b[0]), "r"(b[1]));
}
__device__ __forceinline__ uint32_t sw_off(int row, int col) {
    return (uint32_t)row * 256u + (((uint32_t)col * 2u) ^ (((uint32_t)row & 7u) << 4));
}
// RN round fp32 -> bf16 bits in high half (integer path, ALU pipe)
__device__ __forceinline__ uint32_t rn_hi(uint32_t u) {
    return (u + 0x7FFFu + ((u >> 16) & 1u)) & 0xFFFF0000u;
}
// split two fp32 -> packed bf16x2 hi + lo
__device__ __forceinline__ void split2(float vx, float vy, uint32_t& hi, uint32_t& lo) {
    uint32_t ux = __float_as_uint(vx), uy = __float_as_uint(vy);
    uint32_t rhx = rn_hi(ux), rhy = rn_hi(uy);
    hi = __byte_perm(rhx, rhy, 0x7632);
    float lx = vx - __uint_as_float(rhx);
    float ly = vy - __uint_as_float(rhy);
    uint32_t rlx = rn_hi(__float_as_uint(lx));
    uint32_t rly = rn_hi(__float_as_uint(ly));
    lo = __byte_perm(rlx, rly, 0x7632);
}

// layer GEMM smem (BM=64)
static constexpr int OA_HI = 0;
static constexpr int OA_LO = 16384;
static constexpr int OB_HI = 32768;
static constexpr int OB_LO = 65536;
static constexpr int SMEM_LAYER = 98304;
// head GEMM smem (BM=128)
static constexpr int HA_HI = 0;
static constexpr int HA_LO = 32768;
static constexpr int HB_HI = 65536;
static constexpr int HB_LO = 98304;
static constexpr int SMEM_HEAD = 131072;

// ---------------- weight pre-conversion ----------------------------------------
__global__ void conv_w_k(const float* __restrict__ W, uint16_t* __restrict__ Whi,
                         uint16_t* __restrict__ Wlo, int K, int chunkBase)
{
    int idx = blockIdx.x * blockDim.x + threadIdx.x;
    if (idx >= K * 128) return;
    int k = idx >> 7;
    int n = idx & 127;
    float v = W[idx];
    uint32_t rh = rn_hi(__float_as_uint(v));
    float lf = v - __uint_as_float(rh);
    uint32_t rl = rn_hi(__float_as_uint(lf));
    int c  = k >> 7;
    int kk = k & 127;
    uint32_t o = ((uint32_t)(chunkBase + c) * 32768u + sw_off(kk, n)) >> 1;
    Whi[o] = (uint16_t)(rh >> 16);
    Wlo[o] = (uint16_t)(rl >> 16);
}

// ---------------- head GEMM: BM=128, 512 threads, K=512 ------------------------
__global__ void __launch_bounds__(512, 1)
head_gemm(const float* __restrict__ A,
          const uint4* __restrict__ Whi, const uint4* __restrict__ Wlo,
          const float* __restrict__ bias, float* __restrict__ out)
{
    extern __shared__ char smem[];
    const uint32_t sb = smem_u32(smem);
    const int tid  = threadIdx.x;
    const int wid  = tid >> 5;
    const int lane = tid & 31;
    const int wm = wid & 3;
    const int wn = wid >> 2;
    const int rowBase = blockIdx.x * 128;
    const int M = NN, K = 512;

    float acc[2][4][4];
#pragma unroll
    for (int i = 0; i < 2; i++)
#pragma unroll
        for (int j = 0; j < 4; j++)
#pragma unroll
            for (int q = 0; q < 4; q++) acc[i][j][q] = 0.f;

    const int grp = lane >> 3;
    const int li  = lane & 7;

    float4 pre[8];
#pragma unroll
    for (int t = 0; t < 8; t++) {
        int slot = tid + t * 512;
        int r  = slot >> 5;
        int k4 = (slot & 31) * 4;
        int grow = rowBase + r;
        pre[t] = make_float4(0.f, 0.f, 0.f, 0.f);
        if (grow < M)
            pre[t] = *(const float4*)&A[(size_t)grow * K + k4];
    }

    for (int c = 0; c < 4; c++) {
        if (c > 0) __syncthreads();
#pragma unroll
        for (int t = 0; t < 8; t++) {
            int slot = tid + t * 512;
            int r  = slot >> 5;
            int k4 = (slot & 31) * 4;
            float4 v = pre[t];
            uint32_t h01, l01, h23, l23;
            split2(v.x, v.y, h01, l01);
            split2(v.z, v.w, h23, l23);
            uint32_t o = sw_off(r, k4);
            *(uint32_t*)(smem + HA_HI + o)     = h01;
            *(uint32_t*)(smem + HA_HI + o + 4) = h23;
            *(uint32_t*)(smem + HA_LO + o)     = l01;
            *(uint32_t*)(smem + HA_LO + o + 4) = l23;
        }
        const uint4* srcHi = Whi + (size_t)c * 2048;
        const uint4* srcLo = Wlo + (size_t)c * 2048;
#pragma unroll
        for (int t = 0; t < 4; t++) {
            int slot = tid + t * 512;
            ((uint4*)(smem + HB_HI))[slot] = __ldg(&srcHi[slot]);
            ((uint4*)(smem + HB_LO))[slot] = __ldg(&srcLo[slot]);
        }
        __syncthreads();

        if (c < 3) {
#pragma unroll
            for (int t = 0; t < 8; t++) {
                int slot = tid + t * 512;
                int r  = slot >> 5;
                int k4 = (slot & 31) * 4;
                int grow = rowBase + r;
                pre[t] = make_float4(0.f, 0.f, 0.f, 0.f);
                if (grow < M)
                    pre[t] = *(const float4*)&A[(size_t)grow * K + (c + 1) * 128 + k4];
            }
        }

#pragma unroll
        for (int ks = 0; ks < 8; ks++) {
            int k0 = ks * 16;
            uint32_t ah[2][4], al[2][4];
#pragma unroll
            for (int mt = 0; mt < 2; mt++) {
                int r = wm * 32 + mt * 16 + li + (grp & 1) * 8;
                int kk = k0 + (grp >> 1) * 8;
                uint32_t addr = sb + HA_HI + sw_off(r, kk);
                ldsm_x4(ah[mt], addr);
                ldsm_x4(al[mt], addr + (HA_LO - HA_HI));
            }
            uint32_t bh[4][2], bl[4][2];
#pragma unroll
            for (int ntp = 0; ntp < 2; ntp++) {
                int kk = k0 + li + (grp & 1) * 8;
                int n  = wn * 32 + ntp * 16 + (grp >> 1) * 8;
                uint32_t addr = sb + HB_HI + sw_off(kk, n);
                uint32_t r4[4];
                ldsm_x4_t(r4, addr);
                bh[ntp * 2][0] = r4[0]; bh[ntp * 2][1] = r4[1];
                bh[ntp * 2 + 1][0] = r4[2]; bh[ntp * 2 + 1][1] = r4[3];
                ldsm_x4_t(r4, addr + (HB_LO - HB_HI));
                bl[ntp * 2][0] = r4[0]; bl[ntp * 2][1] = r4[1];
                bl[ntp * 2 + 1][0] = r4[2]; bl[ntp * 2 + 1][1] = r4[3];
            }
#pragma unroll
            for (int mt = 0; mt < 2; mt++)
#pragma unroll
                for (int nt = 0; nt < 4; nt++)
                    mma16816(acc[mt][nt], ah[mt], bh[nt]);
#pragma unroll
            for (int mt = 0; mt < 2; mt++)
#pragma unroll
                for (int nt = 0; nt < 4; nt++)
                    mma16816(acc[mt][nt], ah[mt], bl[nt]);
#pragma unroll
            for (int mt = 0; mt < 2; mt++)
#pragma unroll
                for (int nt = 0; nt < 4; nt++)
                    mma16816(acc[mt][nt], al[mt], bh[nt]);
        }
    }

#pragma unroll
    for (int mt = 0; mt < 2; mt++) {
#pragma unroll
        for (int nt = 0; nt < 4; nt++) {
            int cc = wn * 32 + nt * 8 + (lane & 3) * 2;
            float b0 = __ldg(&bias[cc]);
            float b1 = __ldg(&bias[cc + 1]);
#pragma unroll
            for (int half = 0; half < 2; half++) {
                int row = rowBase + wm * 32 + mt * 16 + half * 8 + (lane >> 2);
                if (row < M) {
                    float v0 = fmaxf(acc[mt][nt][half * 2 + 0] + b0, 0.f);
                    float v1 = fmaxf(acc[mt][nt][half * 2 + 1] + b1, 0.f);
                    *(float2*)&out[(size_t)row * 128 + cc] = make_float2(v0, v1);
                }
            }
        }
    }
}

// ---------------- layer GEMM with fused batched gather --------------------------
template <int MODE, bool TAIL>
__global__ void __launch_bounds__(256, 2)
layer_gemm(const float* __restrict__ x,
           const int* __restrict__ rowstart, const int* __restrict__ adj,
           const uint4* __restrict__ Whi, const uint4* __restrict__ Wlo,
           const float* __restrict__ bias, const float* __restrict__ bf,
           float* __restrict__ out,
           const float* __restrict__ v2, const float* __restrict__ zb,
           float* __restrict__ z, int chunkBase)
{
    extern __shared__ char smem[];
    const uint32_t sb = smem_u32(smem);
    const int tid  = threadIdx.x;
    const int wid  = tid >> 5;
    const int lane = tid & 31;
    const int wm = wid & 1;
    const int wn = wid >> 1;
    const int rowBase = blockIdx.x * 64;
    const int M = NN;

    // ---- fused gather fill: warp w owns rows w*8..w*8+7; 4-edge batches (MLP)
#pragma unroll
    for (int rr = 0; rr < 8; rr++) {
        int r = wid * 8 + rr;
        int n = rowBase + r;
        float4 acc = make_float4(0.f, 0.f, 0.f, 0.f);
        if (n < M) {
            acc = *(const float4*)&x[(size_t)n * 128 + lane * 4];
            int j   = __ldg(&rowstart[n]);
            int end = __ldg(&rowstart[n + 1]);
            for (; j + 4 <= end; j += 4) {
                int s0 = __ldg(&adj[j]);
                int s1 = __ldg(&adj[j + 1]);
                int s2 = __ldg(&adj[j + 2]);
                int s3 = __ldg(&adj[j + 3]);
                float4 v0 = *(const float4*)&x[(size_t)s0 * 128 + lane * 4];
                float4 v1 = *(const float4*)&x[(size_t)s1 * 128 + lane * 4];
                float4 v2l = *(const float4*)&x[(size_t)s2 * 128 + lane * 4];
                float4 v3 = *(const float4*)&x[(size_t)s3 * 128 + lane * 4];
                acc.x += v0.x + v1.x + v2l.x + v3.x;
                acc.y += v0.y + v1.y + v2l.y + v3.y;
                acc.z += v0.z + v1.z + v2l.z + v3.z;
                acc.w += v0.w + v1.w + v2l.w + v3.w;
            }
            for (; j < end; j++) {
                int s = __ldg(&adj[j]);
                float4 v = *(const float4*)&x[(size_t)s * 128 + lane * 4];
                acc.x += v.x; acc.y += v.y; acc.z += v.z; acc.w += v.w;
            }
        }
        uint32_t h01, l01, h23, l23;
        split2(acc.x, acc.y, h01, l01);
        split2(acc.z, acc.w, h23, l23);
        uint32_t o = sw_off(r, lane * 4);
        *(uint32_t*)(smem + OA_HI + o)     = h01;
        *(uint32_t*)(smem + OA_HI + o + 4) = h23;
        *(uint32_t*)(smem + OA_LO + o)     = l01;
        *(uint32_t*)(smem + OA_LO + o + 4) = l23;
    }
    // ---- fill B
    const uint4* srcHi = Whi + (size_t)chunkBase * 2048;
    const uint4* srcLo = Wlo + (size_t)chunkBase * 2048;
#pragma unroll
    for (int t = 0; t < 8; t++) {
        int slot = tid + t * 256;
        ((uint4*)(smem + OB_HI))[slot] = __ldg(&srcHi[slot]);
        ((uint4*)(smem + OB_LO))[slot] = __ldg(&srcLo[slot]);
    }
    __syncthreads();

    float acc[2][4][4];
#pragma unroll
    for (int i = 0; i < 2; i++)
#pragma unroll
        for (int j = 0; j < 4; j++)
#pragma unroll
            for (int q = 0; q < 4; q++) acc[i][j][q] = 0.f;

    const int grp = lane >> 3;
    const int li  = lane & 7;

#pragma unroll
    for (int ks = 0; ks < 8; ks++) {
        int k0 = ks * 16;
        uint32_t ah[2][4], al[2][4];
#pragma unroll
        for (int mt = 0; mt < 2; mt++) {
            int r = wm * 32 + mt * 16 + li + (grp & 1) * 8;
            int kk = k0 + (grp >> 1) * 8;
            uint32_t addr = sb + OA_HI + sw_off(r, kk);
            ldsm_x4(ah[mt], addr);
            ldsm_x4(al[mt], addr + (OA_LO - OA_HI));
        }
        uint32_t bh[4][2], bl[4][2];
#pragma unroll
        for (int ntp = 0; ntp < 2; ntp++) {
            int kk = k0 + li + (grp & 1) * 8;
            int n  = wn * 32 + ntp * 16 + (grp >> 1) * 8;
            uint32_t addr = sb + OB_HI + sw_off(kk, n);
            uint32_t r4[4];
            ldsm_x4_t(r4, addr);
            bh[ntp * 2][0] = r4[0]; bh[ntp * 2][1] = r4[1];
            bh[ntp * 2 + 1][0] = r4[2]; bh[ntp * 2 + 1][1] = r4[3];
            ldsm_x4_t(r4, addr + (OB_LO - OB_HI));
            bl[ntp * 2][0] = r4[0]; bl[ntp * 2][1] = r4[1];
            bl[ntp * 2 + 1][0] = r4[2]; bl[ntp * 2 + 1][1] = r4[3];
        }
#pragma unroll
        for (int mt = 0; mt < 2; mt++)
#pragma unroll
            for (int nt = 0; nt < 4; nt++)
                mma16816(acc[mt][nt], ah[mt], bh[nt]);
#pragma unroll
        for (int mt = 0; mt < 2; mt++)
#pragma unroll
            for (int nt = 0; nt < 4; nt++)
                mma16816(acc[mt][nt], ah[mt], bl[nt]);
#pragma unroll
        for (int mt = 0; mt < 2; mt++)
#pragma unroll
            for (int nt = 0; nt < 4; nt++)
                mma16816(acc[mt][nt], al[mt], bh[nt]);
    }

    // ---- epilogue
    float p[2][2] = {{0.f, 0.f}, {0.f, 0.f}};
#pragma unroll
    for (int mt = 0; mt < 2; mt++) {
#pragma unroll
        for (int nt = 0; nt < 4; nt++) {
            int cc = wn * 32 + nt * 8 + (lane & 3) * 2;
            float b0 = __ldg(&bias[cc]);
            float b1 = __ldg(&bias[cc + 1]);
            float f0 = 0.f, f1 = 0.f;
            if (MODE == 1) { f0 = __ldg(&bf[cc]); f1 = __ldg(&bf[cc + 1]); }
            float w0 = 0.f, w1 = 0.f;
            if (TAIL) { w0 = __ldg(&v2[cc]); w1 = __ldg(&v2[cc + 1]); }
#pragma unroll
            for (int half = 0; half < 2; half++) {
                int row = rowBase + wm * 32 + mt * 16 + half * 8 + (lane >> 2);
                if (row < M) {
                    float v0 = acc[mt][nt][half * 2 + 0];
                    float v1 = acc[mt][nt][half * 2 + 1];
                    if (MODE == 1) {
                        float s = 1.f + (float)(__ldg(&rowstart[row + 1]) - __ldg(&rowstart[row]));
                        v0 += b0 + s * f0;
                        v1 += b1 + s * f1;
                    } else {
                        v0 += b0; v1 += b1;
                    }
                    v0 = fmaxf(v0, 0.f); v1 = fmaxf(v1, 0.f);
                    if (TAIL) {
                        p[mt][half] += v0 * w0 + v1 * w1;
                    } else {
                        *(float2*)&out[(size_t)row * 128 + cc] = make_float2(v0, v1);
                    }
                }
            }
        }
    }

    if (TAIL) {
        __syncthreads();
        float* red = (float*)(smem + OB_HI);
#pragma unroll
        for (int mt = 0; mt < 2; mt++)
#pragma unroll
            for (int half = 0; half < 2; half++) {
                float s = p[mt][half];
                s += __shfl_xor_sync(0xFFFFFFFFu, s, 1);
                s += __shfl_xor_sync(0xFFFFFFFFu, s, 2);
                if ((lane & 3) == 0) {
                    int rl = wm * 32 + mt * 16 + half * 8 + (lane >> 2);
                    red[rl * 4 + wn] = s;
                }
            }
        __syncthreads();
        if (tid < 64) {
            int row = rowBase + tid;
            if (row < M) {
                float s = red[tid * 4 + 0] + red[tid * 4 + 1]
                        + red[tid * 4 + 2] + red[tid * 4 + 3];
                z[row] = s + zb[0];
            }
        }
    }
}

// ---------------- weight folding ------------------------------------------------
__global__ void fold_W_k(const float* __restrict__ L1, const float* __restrict__ G2,
                         float* __restrict__ WF)
{
    int idx = blockIdx.x * blockDim.x + threadIdx.x;
    int i = idx >> 7, j = idx & 127;
    float s = 0.f;
    for (int k = 0; k < 128; k++)
        s = fmaf(L1[i * 128 + k], G2[k * 128 + j], s);
    WF[idx] = s;
}
__global__ void fold_b_k(const float* __restrict__ bl1, const float* __restrict__ G2,
                         float* __restrict__ bf)
{
    int j = threadIdx.x;
    float s = 0.f;
    for (int i = 0; i < 128; i++)
        s = fmaf(bl1[i], G2[i * 128 + j], s);
    bf[j] = s;
}
__global__ void fold_t_k(const float* __restrict__ L2, const float* __restrict__ T,
                         const float* __restrict__ bl2, const float* __restrict__ bt,
                         float* __restrict__ v2, float* __restrict__ zb)
{
    int i = threadIdx.x;
    float s = 0.f;
    for (int k = 0; k < 128; k++)
        s = fmaf(L2[i * 128 + k], T[k], s);
    v2[i] = s;
    if (i == 0) {
        float z = bt[0];
        for (int k = 0; k < 128; k++) z = fmaf(bl2[k], T[k], z);
        zb[0] = z;
    }
}

// ---------------- CSR build ----------------------------------------------------
__global__ void zero_deg_k(int* __restrict__ deg)
{
    int i = blockIdx.x * blockDim.x + threadIdx.x;
    if (i < NN) deg[i] = 0;
}
__global__ void degree_k(const int* __restrict__ ei, int* __restrict__ deg)
{
    int e = blockIdx.x * blockDim.x + threadIdx.x;
    if (e < EE) atomicAdd(&deg[ei[EE + e]], 1);
}
__global__ void scan_k(const int* __restrict__ deg, int* __restrict__ rowstart,
                       int* __restrict__ cursor)
{
    __shared__ int sh[1024];
    const int tid = threadIdx.x;
    const int CH  = (NN + 1023) / 1024;
    const int base = tid * CH;

    int s = 0;
    for (int i = 0; i < CH; i++) {
        int idx = base + i;
        if (idx < NN) s += deg[idx];
    }
    sh[tid] = s;
    __syncthreads();
    for (int o = 1; o < 1024; o <<= 1) {
        int v = (tid >= o) ? sh[tid - o] : 0;
        __syncthreads();
        sh[tid] += v;
        __syncthreads();
    }
    int run = sh[tid] - s;
    for (int i = 0; i < CH; i++) {
        int idx = base + i;
        if (idx < NN) {
            rowstart[idx] = run;
            cursor[idx]   = run;
            run += deg[idx];
        }
    }
    if (tid == 1023) rowstart[NN] = sh[1023];
}
__global__ void fill_k(const int* __restrict__ ei, int* __restrict__ cursor,
                       int* __restrict__ adj)
{
    int e = blockIdx.x * blockDim.x + threadIdx.x;
    if (e < EE) {
        int s = ei[e];
        int d = ei[EE + e];
        int p = atomicAdd(&cursor[d], 1);
        adj[p] = s;
    }
}

// ---------------- BN -----------------------------------------------------------
__global__ void stats_k(const float* __restrict__ z, float* __restrict__ stats)
{
    __shared__ float sh[1024];
    int tid = threadIdx.x;

    float s = 0.f;
    for (int i = tid; i < NN; i += 1024) s += z[i];
    sh[tid] = s;
    __syncthreads();
    for (int o = 512; o > 0; o >>= 1) {
        if (tid < o) sh[tid] += sh[tid + o];
        __syncthreads();
    }
    float mu = sh[0] / (float)NN;
    __syncthreads();

    float v = 0.f;
    for (int i = tid; i < NN; i += 1024) {
        float d = z[i] - mu;
        v += d * d;
    }
    sh[tid] = v;
    __syncthreads();
    for (int o = 512; o > 0; o >>= 1) {
        if (tid < o) sh[tid] += sh[tid + o];
        __syncthreads();
    }
    if (tid == 0) {
        stats[0] = mu;
        stats[1] = rsqrtf(sh[0] / (float)NN + 1e-5f);
    }
}
__global__ void bn_k(const float* __restrict__ z, const float* __restrict__ stats,
                     const float* __restrict__ gamma, const float* __restrict__ beta,
                     float* __restrict__ out)
{
    int i = blockIdx.x * blockDim.x + threadIdx.x;
    if (i < NN) {
        out[i] = (z[i] - stats[0]) * stats[1] * gamma[0] + beta[0];
    }
}

// ---------------- launcher ------------------------------------------------------
extern "C" void kernel_launch(void* const* d_in, const int* in_sizes, int n_in,
                              void* d_out, int out_size)
{
    const float* feature = (const float*)d_in[0];
    const int*   ei      = (const int*)d_in[1];
    const float* head_W  = (const float*)d_in[2];
    const float* head_b  = (const float*)d_in[3];
    const float* gin_W1  = (const float*)d_in[4];
    const float* gin_b1  = (const float*)d_in[5];
    const float* lin_W1  = (const float*)d_in[6];
    const float* lin_b1  = (const float*)d_in[7];
    const float* gin_W2  = (const float*)d_in[8];
    const float* gin_b2  = (const float*)d_in[9];
    const float* lin_W2  = (const float*)d_in[10];
    const float* lin_b2  = (const float*)d_in[11];
    const float* tail_W  = (const float*)d_in[12];
    const float* tail_b  = (const float*)d_in[13];
    const float* bn_g    = (const float*)d_in[14];
    const float* bn_b    = (const float*)d_in[15];
    float* out = (float*)d_out;

    float *xp, *hp, *zp, *stp, *wfp, *bfp, *v2p, *zbp;
    int *degp, *rsp, *curp, *adjp;
    uint16_t *whip, *wlop;
    cudaGetSymbolAddress((void**)&xp,   g_x);
    cudaGetSymbolAddress((void**)&hp,   g_h);
    cudaGetSymbolAddress((void**)&zp,   g_z);
    cudaGetSymbolAddress((void**)&stp,  g_stats);
    cudaGetSymbolAddress((void**)&degp, g_deg);
    cudaGetSymbolAddress((void**)&rsp,  g_rowstart);
    cudaGetSymbolAddress((void**)&curp, g_cursor);
    cudaGetSymbolAddress((void**)&adjp, g_adj);
    cudaGetSymbolAddress((void**)&wfp,  g_WF);
    cudaGetSymbolAddress((void**)&bfp,  g_bf);
    cudaGetSymbolAddress((void**)&v2p,  g_v2);
    cudaGetSymbolAddress((void**)&zbp,  g_zb);
    cudaGetSymbolAddress((void**)&whip, g_Whi);
    cudaGetSymbolAddress((void**)&wlop, g_Wlo);

    static cudaStream_t sA = nullptr, sB = nullptr;
    static cudaEvent_t e0, e1, e2;
    if (!sA) {
        cudaStreamCreateWithFlags(&sA, cudaStreamNonBlocking);
        cudaStreamCreateWithFlags(&sB, cudaStreamNonBlocking);
        cudaEventCreateWithFlags(&e0, cudaEventDisableTiming);
        cudaEventCreateWithFlags(&e1, cudaEventDisableTiming);
        cudaEventCreateWithFlags(&e2, cudaEventDisableTiming);
        cudaFuncSetAttribute(head_gemm, cudaFuncAttributeMaxDynamicSharedMemorySize, SMEM_HEAD);
        cudaFuncSetAttribute(layer_gemm<0, false>, cudaFuncAttributeMaxDynamicSharedMemorySize, SMEM_LAYER);
        cudaFuncSetAttribute(layer_gemm<1, true>,  cudaFuncAttributeMaxDynamicSharedMemorySize, SMEM_LAYER);
    }

    const int headGrid  = (NN + 127) / 128;
    const int layerGrid = (NN + 63) / 64;
    const int edgeGrid  = (EE + 255) / 256;
    const int nodeGrid  = (NN + 255) / 256;

    // ---- fork side work ----
    cudaEventRecord(e0, 0);

    cudaStreamWaitEvent(sA, e0, 0);
    zero_deg_k<<<nodeGrid, 256, 0, sA>>>(degp);
    degree_k<<<edgeGrid, 256, 0, sA>>>(ei, degp);
    scan_k<<<1, 1024, 0, sA>>>(degp, rsp, curp);
    fill_k<<<edgeGrid, 256, 0, sA>>>(ei, curp, adjp);
    cudaEventRecord(e1, sA);

    cudaStreamWaitEvent(sB, e0, 0);
    fold_W_k<<<64, 256, 0, sB>>>(lin_W1, gin_W2, wfp);
    fold_b_k<<<1, 128, 0, sB>>>(lin_b1, gin_W2, bfp);
    fold_t_k<<<1, 128, 0, sB>>>(lin_W2, tail_W, lin_b2, tail_b, v2p, zbp);
    conv_w_k<<<(128 * 128 + 255) / 256, 256, 0, sB>>>(gin_W1, whip, wlop, 128, 4);
    conv_w_k<<<(128 * 128 + 255) / 256, 256, 0, sB>>>(wfp,    whip, wlop, 128, 5);
    cudaEventRecord(e2, sB);

    // main: head weight conversion + head GEMM
    conv_w_k<<<(512 * 128 + 255) / 256, 256>>>(head_W, whip, wlop, 512, 0);
    head_gemm<<<headGrid, 512, SMEM_HEAD>>>(
        feature, (const uint4*)whip, (const uint4*)wlop, head_b, xp);

    // GIN layer 1 (fused gather + GEMM)
    cudaStreamWaitEvent(0, e1, 0);
    cudaStreamWaitEvent(0, e2, 0);
    layer_gemm<0, false><<<layerGrid, 256, SMEM_LAYER>>>(
        xp, rsp, adjp, (const uint4*)whip, (const uint4*)wlop,
        gin_b1, nullptr, hp, nullptr, nullptr, nullptr, 4);

    // layer 2 (folded) + fused tail -> z
    layer_gemm<1, true><<<layerGrid, 256, SMEM_LAYER>>>(
        hp, rsp, adjp, (const uint4*)whip, (const uint4*)wlop,
        gin_b2, bfp, nullptr, v2p, zbp, zp, 5);

    // BN
    stats_k<<<1, 1024>>>(zp, stp);
    bn_k<<<nodeGrid, 256>>>(zp, stp, bn_g, bn_b, out);
}